// round 5
// baseline (speedup 1.0000x reference)
#include <cuda_runtime.h>
#include <cstdint>

#define BN 64
#define PP 8732
#define CC 81
#define KT 16
#define THRESH 0.5f
#define VAR0 0.1f
#define VAR1 0.2f

#define NR (BN * PP)             // 558848 total rows
#define RPB 512                  // rows per CE block (128 per warp)
#define NCE ((NR + RPB - 1) / RPB)   // 1092 CE blocks
#define NCH 16
#define CHUNK 546
#define MBLK (BN * NCH)          // 1024 matchA blocks
#define TPB_POST 512
#define PPAD 9216

// ---------------- scratch ----------------
__device__ float g_bto[NR];
__device__ int   g_bti[NR];
__device__ float g_lse[NR];
__device__ float g_lm[NR];
__device__ unsigned long long g_best[BN * KT];   // idempotent atomicMax accumulator
__device__ float g_loss_l[BN];
__device__ float g_loss_c[BN];
__device__ int   g_num_pos[BN];
__device__ int   g_done;                          // self-resetting counter

// ---------------- PTX helpers ----------------
static __device__ __forceinline__ unsigned su32(const void* p) {
    return (unsigned)__cvta_generic_to_shared(p);
}
#define MBAR_INIT(a, c) \
    asm volatile("mbarrier.init.shared.b64 [%0], %1;" :: "r"(a), "r"(c) : "memory")
#define MBAR_EXPECT(a, n) \
    asm volatile("mbarrier.arrive.expect_tx.shared.b64 _, [%0], %1;" :: "r"(a), "r"(n) : "memory")
#define BULK_G2S(dst, src, n, mbar) \
    asm volatile("cp.async.bulk.shared::cta.global.mbarrier::complete_tx::bytes [%0], [%1], %2, [%3];" \
                 :: "r"(dst), "l"(src), "r"(n), "r"(mbar) : "memory")
#define MBAR_WAITP(a, par) do {                                                     \
    unsigned _done = 0;                                                             \
    while (!_done) {                                                                \
        asm volatile("{\n\t.reg .pred p;\n\t"                                       \
            "mbarrier.try_wait.parity.acquire.cta.shared::cta.b64 p, [%1], %2, 0x989680;\n\t" \
            "selp.b32 %0, 1, 0, p;\n\t}"                                            \
            : "=r"(_done) : "r"(a), "r"((unsigned)(par)) : "memory");               \
    }                                                                               \
} while (0)

// ---------------- kernel 1: fused CE (warp-per-row) + matchA ----------------
__global__ __launch_bounds__(128, 8) void k_big(const float* __restrict__ conf,
                                                const float* __restrict__ priors,
                                                const float* __restrict__ targets) {
    const int blk = blockIdx.x;
    const int tid = threadIdx.x;

    if (blk < NCE) {
        // ------- CE role: warp per row, coalesced, no smem -------
        const int wid = tid >> 5;
        const int lane = tid & 31;
        const bool l3 = lane < (CC - 64);            // 17 lanes
        int g = blk * RPB + wid * 128;
        const int gend0 = g + 128;
        const int gend = (gend0 < NR) ? gend0 : NR;

        for (; g < gend; g += 2) {
            const float* r0 = conf + (size_t)g * CC;
            const float* r1 = r0 + CC;
            // 6 independent coalesced loads
            const float a0 = r0[lane];
            const float b0 = r0[lane + 32];
            const float c0 = l3 ? r0[lane + 64] : 0.0f;
            const float a1 = r1[lane];
            const float b1 = r1[lane + 32];
            const float c1 = l3 ? r1[lane + 64] : 0.0f;

            float s0 = __expf(a0) + __expf(b0) + (l3 ? __expf(c0) : 0.0f);
            float s1 = __expf(a1) + __expf(b1) + (l3 ? __expf(c1) : 0.0f);
#pragma unroll
            for (int o = 16; o; o >>= 1) {
                s0 += __shfl_xor_sync(0xFFFFFFFFu, s0, o);
                s1 += __shfl_xor_sync(0xFFFFFFFFu, s1, o);
            }
            if (lane == 0) {
                const float lse0 = __logf(s0);
                const float lse1 = __logf(s1);
                // g is even: float2 stores
                *(float2*)(g_lse + g) = make_float2(lse0, lse1);
                *(float2*)(g_lm + g) = make_float2(lse0 - a0, lse1 - a1);
            }
        }
    } else {
        // ------- matchA role -------
        __shared__ float s_t[KT][4];
        __shared__ float s_area[KT];
        __shared__ unsigned long long s_best[KT];

        const int q = blk - NCE;
        const int b = q >> 4;
        const int c = q & 15;
        if (tid < KT) {
            const float* tg = targets + (size_t)(b * KT + tid) * 6;
            s_t[tid][0] = tg[2]; s_t[tid][1] = tg[3];
            s_t[tid][2] = tg[4]; s_t[tid][3] = tg[5];
            s_area[tid] = (tg[4] - tg[2]) * (tg[5] - tg[3]);
            s_best[tid] = 0ull;
        }
        __syncthreads();

        const int p0 = c * CHUNK;
        const int p1 = (p0 + CHUNK < PP) ? p0 + CHUNK : PP;

        for (int p = p0 + tid; p < p1; p += 128) {
            const float4 pr = ((const float4*)priors)[p];
            const float parea = (pr.z - pr.x) * (pr.w - pr.y);
            float bestov = -1.0f;
            int besti = 0;
#pragma unroll
            for (int k = 0; k < KT; k++) {
                float ix = fminf(s_t[k][2], pr.z) - fmaxf(s_t[k][0], pr.x);
                float iy = fminf(s_t[k][3], pr.w) - fmaxf(s_t[k][1], pr.y);
                float inter = fmaxf(ix, 0.0f) * fmaxf(iy, 0.0f);
                float ov = inter / (s_area[k] + parea - inter);
                if (ov > bestov) { bestov = ov; besti = k; }
                unsigned long long key =
                    ((unsigned long long)__float_as_uint(ov) << 32) |
                    (unsigned long long)(0xFFFFFFFFu - (unsigned)p);
                atomicMax(&s_best[k], key);
            }
            g_bto[b * PP + p] = bestov;
            g_bti[b * PP + p] = besti;
        }
        __syncthreads();
        if (tid < KT)
            atomicMax(&g_best[b * KT + tid], s_best[tid]);
        // block (NCE) zeroes nothing; g_done self-resets; g_loss arrays overwritten below
    }
}

// ---------------- kernel 2: force-assign + smooth-L1 + pos-CE + topk + finalize ----------------
__global__ __launch_bounds__(TPB_POST) void k_post(const float* __restrict__ conf,
                                                   const float* __restrict__ loc,
                                                   const float* __restrict__ priors,
                                                   const float* __restrict__ targets,
                                                   float* __restrict__ out) {
    const int b = blockIdx.x;
    const int tid = threadIdx.x;
    const int lane = tid & 31;
    const int bPP = b * PP;

    __shared__ __align__(16) float s_lm[PP];
    __shared__ int s_hist[256];
    __shared__ int s_cum[256];
    __shared__ float s_redf[TPB_POST];
    __shared__ int s_redi[TPB_POST];
    __shared__ float s_t[KT][4];
    __shared__ int s_lab[KT];
    __shared__ unsigned s_prefix;
    __shared__ int s_rem;
    __shared__ float s_spos;
    __shared__ __align__(8) unsigned long long s_mbar;

    const unsigned mb = su32(&s_mbar);
    if (tid == 0) MBAR_INIT(mb, 1);
    if (tid < KT) {
        const float* tg = targets + (size_t)(b * KT + tid) * 6;
        s_lab[tid] = (int)tg[1];
        s_t[tid][0] = tg[2]; s_t[tid][1] = tg[3];
        s_t[tid][2] = tg[4]; s_t[tid][3] = tg[5];
    }
    __syncthreads();
    if (tid == 0) {
        MBAR_EXPECT(mb, (unsigned)(PP * 4));
        BULK_G2S(su32(s_lm), g_lm + bPP, (unsigned)(PP * 4), mb);
        for (int k = 0; k < KT; k++) {   // sequential force-assign, last write wins
            unsigned long long key = g_best[b * KT + k];
            int p = (int)(0xFFFFFFFFu - (unsigned)(key & 0xFFFFFFFFull));
            g_bti[bPP + p] = k;
            g_bto[bPP + p] = __uint_as_float((unsigned)(key >> 32));
        }
    }
    __syncthreads();
    MBAR_WAITP(mb, 0);

    // main pass
    float lsum = 0.0f, spos = 0.0f;
    int cnt = 0;
    for (int p = tid; p < PP; p += TPB_POST) {
        const float ov = g_bto[bPP + p];
        const int k = g_bti[bPP + p];
        const int ct = (ov < THRESH) ? 0 : s_lab[k];
        if (ct > 0) {
            cnt++;
            s_lm[p] = 0.0f;
            spos += g_lse[bPP + p] - conf[(size_t)(bPP + p) * CC + ct];
            const float4 pr = ((const float4*)priors)[p];
            const float pcx = 0.5f * (pr.x + pr.z), pcy = 0.5f * (pr.y + pr.w);
            const float pw = pr.z - pr.x, ph = pr.w - pr.y;
            const float mx1 = s_t[k][0], my1 = s_t[k][1];
            const float mx2 = s_t[k][2], my2 = s_t[k][3];
            float g0 = (0.5f * (mx1 + mx2) - pcx) / (VAR0 * pw);
            float g1 = (0.5f * (my1 + my2) - pcy) / (VAR0 * ph);
            float g2 = logf((mx2 - mx1) / pw) / VAR1;
            float g3 = logf((my2 - my1) / ph) / VAR1;
            const float4 ld = ((const float4*)loc)[bPP + p];
            float d, ad;
            d = ld.x - g0; ad = fabsf(d); lsum += (ad < 1.0f) ? 0.5f * d * d : ad - 0.5f;
            d = ld.y - g1; ad = fabsf(d); lsum += (ad < 1.0f) ? 0.5f * d * d : ad - 0.5f;
            d = ld.z - g2; ad = fabsf(d); lsum += (ad < 1.0f) ? 0.5f * d * d : ad - 0.5f;
            d = ld.w - g3; ad = fabsf(d); lsum += (ad < 1.0f) ? 0.5f * d * d : ad - 0.5f;
        }
    }
    s_redi[tid] = cnt;
    s_redf[tid] = spos;
    __syncthreads();
    for (int s = TPB_POST / 2; s > 0; s >>= 1) {
        if (tid < s) { s_redi[tid] += s_redi[tid + s]; s_redf[tid] += s_redf[tid + s]; }
        __syncthreads();
    }
    const int npos = s_redi[0];
    if (tid == 0) s_spos = s_redf[0];
    __syncthreads();
    s_redf[tid] = lsum;
    __syncthreads();
    for (int s = TPB_POST / 2; s > 0; s >>= 1) {
        if (tid < s) s_redf[tid] += s_redf[tid + s];
        __syncthreads();
    }
    if (tid == 0) {
        g_loss_l[b] = s_redf[0];
        g_num_pos[b] = npos;
    }

    int k = 3 * npos;
    if (k > PP - 1) k = PP - 1;

    float T = 0.0f;
    if (k > 0) {
        if (tid == 0) { s_prefix = 0u; s_rem = k; }
        if (tid < 256) s_hist[tid] = 0;
        __syncthreads();
        for (int shift = 24; shift >= 0; shift -= 8) {
            const unsigned pref = s_prefix;
            const int rem = s_rem;
            const unsigned hm = (shift == 24) ? 0u : (0xFFFFFFFFu << (shift + 8));
            for (int p = tid; p < PPAD; p += TPB_POST) {
                const bool v = p < PP;
                const unsigned bits = v ? __float_as_uint(s_lm[p]) : 0u;
                const int bin = (bits >> shift) & 255;
                const bool pred = v && ((bits & hm) == pref);
                unsigned m = __match_any_sync(0xFFFFFFFFu, bin) &
                             __ballot_sync(0xFFFFFFFFu, pred);
                if (pred && lane == (__ffs(m) - 1))
                    atomicAdd(&s_hist[bin], __popc(m));
            }
            __syncthreads();
            if (tid < 256) s_cum[tid] = s_hist[tid];
            __syncthreads();
            for (int off = 1; off < 256; off <<= 1) {
                int v2 = 0;
                if (tid < 256 && tid + off < 256) v2 = s_cum[tid + off];
                __syncthreads();
                if (tid < 256) s_cum[tid] += v2;
                __syncthreads();
            }
            if (tid < 256) {
                const int above = (tid == 255) ? 0 : s_cum[tid + 1];
                if (s_cum[tid] >= rem && above < rem) {
                    s_prefix = pref | ((unsigned)tid << shift);
                    s_rem = rem - above;
                }
                s_hist[tid] = 0;
            }
            __syncthreads();
        }
        const unsigned t = s_prefix;
        float sumgt = 0.0f;
        int cntgt = 0;
        for (int p = tid; p < PP; p += TPB_POST) {
            const float lm = s_lm[p];
            if (__float_as_uint(lm) > t) { sumgt += lm; cntgt++; }
        }
        s_redf[tid] = sumgt;
        s_redi[tid] = cntgt;
        __syncthreads();
        for (int s = TPB_POST / 2; s > 0; s >>= 1) {
            if (tid < s) { s_redf[tid] += s_redf[tid + s]; s_redi[tid] += s_redi[tid + s]; }
            __syncthreads();
        }
        T = s_redf[0] + (float)(k - s_redi[0]) * __uint_as_float(t);
    }
    if (tid == 0) {
        g_loss_c[b] = s_spos + T;
        __threadfence();
        const int old = atomicAdd(&g_done, 1);
        if (old == BN - 1) {
            // last block finalizes
            float sl = 0.0f, sc = 0.0f;
            int sn = 0;
            for (int i = 0; i < BN; i++) {
                sl += g_loss_l[i];
                sc += g_loss_c[i];
                sn += g_num_pos[i];
            }
            const float n = fmaxf((float)sn, 1.0f);
            out[0] = sl / n;
            out[1] = sc / n;
            g_done = 0;   // self-reset for next replay
        }
    }
}

extern "C" void kernel_launch(void* const* d_in, const int* in_sizes, int n_in,
                              void* d_out, int out_size) {
    const float* loc = (const float*)d_in[0];
    const float* conf = (const float*)d_in[1];
    const float* priors = (const float*)d_in[2];
    const float* targets = (const float*)d_in[3];
    float* out = (float*)d_out;

    k_big<<<NCE + MBLK, 128>>>(conf, priors, targets);
    k_post<<<BN, TPB_POST>>>(conf, loc, priors, targets, out);
}